// round 5
// baseline (speedup 1.0000x reference)
// AttentiveLinear as ONE symmetric-reduced GEMM [8192 x 8384] x [8384 x 128]:
//   y[n,o] = sum_{j<i} x_j x_i (Ww[j,i,o]+Ww[i,j,o]) + sum_i x_i^2 Ww[i,i,o]
//          + sum_i x_i (Wb[i,o]+bw[i,o]) + bb[o]
// Build target is plain sm_103 (no 'a') -> tcgen05 unavailable; use sm_80-era
// mma.sync m16n8k8 tf32 (legacy HMMA pipe). A operand built on the fly in SMEM.
#include <cuda_runtime.h>
#include <cstdint>
#include <cstddef>

// Ws[t][o]: symmetric-folded, tf32-rounded B operand. t<8128 pairs (j<i),
// 8128..8255 diagonal, 8256..8383 linear/bias rows. 4.29 MB (L2-resident).
__device__ __align__(16) float g_Ws[8384 * 128];
__device__ uint16_t g_idx[8384];   // (j<<8)|i ; j==255 marks bias rows

__device__ __forceinline__ float tf32_rna(float v) {
    uint32_t u;
    asm("cvt.rna.tf32.f32 %0, %1;" : "=r"(u) : "f"(v));
    return __uint_as_float(u);
}

// ---------------- prep kernels ----------------
__global__ void k_previdx() {
    int t = blockIdx.x * 256 + threadIdx.x;
    if (t >= 8384) return;
    uint16_t v;
    if (t < 8128) {
        int j = 0, s = 0;
        while (s + 127 - j <= t) { s += 127 - j; j++; }
        int i = j + 1 + (t - s);
        v = (uint16_t)((j << 8) | i);
    } else if (t < 8256) {
        int i = t - 8128;
        v = (uint16_t)((i << 8) | i);
    } else {
        v = (uint16_t)((255 << 8) | (t - 8256));
    }
    g_idx[t] = v;
}

__global__ void k_prepW(const float* __restrict__ Ww, const float* __restrict__ Wb,
                        const float* __restrict__ bw) {
    int t = blockIdx.x;
    int o = threadIdx.x;
    float v;
    if (t < 8128) {
        uint32_t e = g_idx[t];          // k_previdx ran earlier in-stream
        int j = e >> 8, i = e & 255;
        v = Ww[(size_t)j * 16384 + i * 128 + o] + Ww[(size_t)i * 16384 + j * 128 + o];
    } else if (t < 8256) {
        int i = t - 8128;
        v = Ww[(size_t)i * 16384 + i * 128 + o];
    } else {
        int i = t - 8256;
        v = Wb[i * 128 + o] + bw[i * 128 + o];
    }
    g_Ws[(size_t)t * 128 + o] = tf32_rna(v);
}

// ---------------- main kernel ----------------
// SMEM (bytes): X[64][132]f  @0      (33792)
//               idx u16x8384 @33792  (16768)
//               A[2][64][36]f @50560 (18432)   stride 36 -> conflict-free frags
//               B[2][32][136]f @68992 (34816)  stride 136 -> conflict-free frags
static constexpr int SMEM_TOTAL = 103808;
static constexpr int NKB = 262;          // 8384 / 32

__global__ void __launch_bounds__(128) k_main(const float* __restrict__ x,
                                              const float* __restrict__ bb,
                                              float* __restrict__ y) {
    extern __shared__ char smem[];
    float*    sX   = (float*)(smem);
    uint16_t* sIdx = (uint16_t*)(smem + 33792);
    float*    sA   = (float*)(smem + 50560);
    float*    sB   = (float*)(smem + 68992);

    const int tid  = threadIdx.x;
    const int m0   = blockIdx.x * 64;
    const int lane = tid & 31, wid = tid >> 5;
    const int wm = wid & 1, wn = wid >> 1;      // warp tile 32(M) x 64(N)
    const int gid = lane >> 2, tg = lane & 3;

    // Load X tile: 64 rows x 128 floats (smem stride 132)
    {
        const int r = tid >> 1, h = (tid & 1) * 16;
        const float4* src = (const float4*)(x + (size_t)(m0 + r) * 128) + h;
        float4* dst = (float4*)(sX + r * 132) + h;
#pragma unroll
        for (int c = 0; c < 16; c++) dst[c] = src[c];
    }
    // Load index table
    {
        const uint32_t* s = (const uint32_t*)g_idx;
        uint32_t* d = (uint32_t*)sIdx;
        for (int k = tid; k < 4192; k += 128) d[k] = s[k];
    }
    __syncthreads();

    // A builder: 128 thr = 32 t'-cols x 4 row-groups of 16
    auto buildA = [&](int kb, int bf) {
        const int tp = tid & 31;
        const int r0 = (tid >> 5) * 16;
        const uint32_t e = sIdx[kb * 32 + tp];
        const int j = e >> 8, i = e & 255;
        const bool bias = (j == 255);
        float* dst = sA + bf * 2304 + tp;
        const float* Xi = sX + i;
        const float* Xj = sX + (bias ? 0 : j);
#pragma unroll
        for (int r = 0; r < 16; r++) {
            const float xv = Xi[(r0 + r) * 132];
            const float xj = bias ? 1.0f : Xj[(r0 + r) * 132];
            dst[(r0 + r) * 36] = tf32_rna(xv * xj);
        }
    };
    auto ldgB = [&](int kb, float4* rb) {
        const int r = tid >> 2, q = tid & 3;
        const float4* src = (const float4*)(g_Ws + (size_t)(kb * 32 + r) * 128) + q * 8;
#pragma unroll
        for (int c = 0; c < 8; c++) rb[c] = src[c];
    };
    auto stsB = [&](int bf, const float4* rb) {
        const int r = tid >> 2, q = tid & 3;
        float4* dst = (float4*)(sB + bf * 4352 + r * 136 + q * 32);
#pragma unroll
        for (int c = 0; c < 8; c++) dst[c] = rb[c];
    };

    // Prologue: stage block 0
    {
        float4 rb[8];
        ldgB(0, rb);
        buildA(0, 0);
        stsB(0, rb);
    }
    __syncthreads();

    float acc[2][8][4] = {};
    float4 rb[8];

    for (int kb = 0; kb < NKB; kb++) {
        const int cur = kb & 1, nxt = cur ^ 1;
        const bool pf = (kb + 1 < NKB);
        if (pf) ldgB(kb + 1, rb);       // hide L2 latency under build+mma
        if (pf) buildA(kb + 1, nxt);

        const float* A = sA + cur * 2304;
        const float* B = sB + cur * 4352;
#pragma unroll
        for (int ks = 0; ks < 4; ks++) {
            const int kt = ks * 8;
            uint32_t a[2][4], b[8][2];
#pragma unroll
            for (int mt = 0; mt < 2; mt++) {
                const int row = wm * 32 + mt * 16 + gid;
                a[mt][0] = __float_as_uint(A[row * 36 + kt + tg]);
                a[mt][1] = __float_as_uint(A[(row + 8) * 36 + kt + tg]);
                a[mt][2] = __float_as_uint(A[row * 36 + kt + tg + 4]);
                a[mt][3] = __float_as_uint(A[(row + 8) * 36 + kt + tg + 4]);
            }
#pragma unroll
            for (int nt = 0; nt < 8; nt++) {
                const int col = wn * 64 + nt * 8 + gid;
                b[nt][0] = __float_as_uint(B[(kt + tg) * 136 + col]);
                b[nt][1] = __float_as_uint(B[(kt + tg + 4) * 136 + col]);
            }
#pragma unroll
            for (int mt = 0; mt < 2; mt++)
#pragma unroll
                for (int nt = 0; nt < 8; nt++)
                    asm volatile(
                        "mma.sync.aligned.m16n8k8.row.col.f32.tf32.tf32.f32 "
                        "{%0,%1,%2,%3}, {%4,%5,%6,%7}, {%8,%9}, {%0,%1,%2,%3};"
                        : "+f"(acc[mt][nt][0]), "+f"(acc[mt][nt][1]),
                          "+f"(acc[mt][nt][2]), "+f"(acc[mt][nt][3])
                        : "r"(a[mt][0]), "r"(a[mt][1]), "r"(a[mt][2]), "r"(a[mt][3]),
                          "r"(b[nt][0]), "r"(b[nt][1]));
        }
        if (pf) stsB(nxt, rb);
        __syncthreads();
    }

    // Epilogue: add bb, store
    const int mb = m0 + wm * 32 + gid;
#pragma unroll
    for (int mt = 0; mt < 2; mt++) {
#pragma unroll
        for (int nt = 0; nt < 8; nt++) {
            const int n = wn * 64 + nt * 8 + tg * 2;
            const float b0 = __ldg(bb + n), b1 = __ldg(bb + n + 1);
            float* r0p = y + (size_t)(mb + mt * 16) * 128 + n;
            float* r1p = r0p + 8 * 128;
            ((float2*)r0p)[0] = make_float2(acc[mt][nt][0] + b0, acc[mt][nt][1] + b1);
            ((float2*)r1p)[0] = make_float2(acc[mt][nt][2] + b0, acc[mt][nt][3] + b1);
        }
    }
}

extern "C" void kernel_launch(void* const* d_in, const int* in_sizes, int n_in,
                              void* d_out, int out_size) {
    const float* x  = (const float*)d_in[0];
    const float* Wb = (const float*)d_in[1];
    const float* bb = (const float*)d_in[2];
    const float* Ww = (const float*)d_in[3];
    const float* bw = (const float*)d_in[4];
    float* y = (float*)d_out;

    static bool attr_set = false;
    if (!attr_set) {
        cudaFuncSetAttribute(k_main, cudaFuncAttributeMaxDynamicSharedMemorySize, SMEM_TOTAL);
        attr_set = true;
    }

    k_previdx<<<33, 256>>>();
    k_prepW<<<8384, 128>>>(Ww, Wb, bw);
    k_main<<<128, 128, SMEM_TOTAL>>>(x, bb, y);
}

// round 6
// speedup vs baseline: 1.9349x; 1.9349x over previous
// AttentiveLinear as ONE symmetric-reduced GEMM [8192 x 8384] x [8384 x 128]:
//   y[n,o] = sum_{j<i} x_j x_i (Ww[j,i,o]+Ww[i,j,o]) + sum_i x_i^2 Ww[i,i,o]
//          + sum_i x_i (Wb[i,o]+bw[i,o]) + bb[o]
// Target is plain sm_103 (no 'a'): tcgen05 unavailable -> mma.sync m16n8k8 tf32.
// R5: fragment-major SMEM layouts (LDS.128 everywhere), 256 thr / 8 warps,
//     cp.async B staging, prep folded to one kernel (ncu now lands on k_main).
#include <cuda_runtime.h>
#include <cstdint>
#include <cstddef>

// g_Ws[t][f]: symmetric-folded tf32 B operand, PERMUTED within each row:
//   f = (o&7)*16 + (o>>3)  so consumer B-frags are contiguous 16B chunks.
__device__ __align__(16) float g_Ws[8384 * 128];
__device__ uint16_t g_idx[8384];   // (j<<8)|i ; j==255 marks linear/bias rows

__device__ __forceinline__ float tf32_rna(float v) {
    uint32_t u;
    asm("cvt.rna.tf32.f32 %0, %1;" : "=r"(u) : "f"(v));
    return __uint_as_float(u);
}
__device__ __forceinline__ uint32_t smem_u32(const void* p) {
    uint32_t a;
    asm("{ .reg .u64 t; cvta.to.shared.u64 t, %1; cvt.u32.u64 %0, t; }" : "=r"(a) : "l"(p));
    return a;
}

// ---------------- prep kernel (index gen + fold + permute, one launch) ----
__global__ void k_prepW(const float* __restrict__ Ww, const float* __restrict__ Wb,
                        const float* __restrict__ bw) {
    __shared__ int sj, si;
    const int t = blockIdx.x, o = threadIdx.x;
    if (threadIdx.x == 0) {
        int j, i;
        if (t < 8128) {                      // strict upper pairs (j<i)
            j = 0; int s = 0;
            while (s + 127 - j <= t) { s += 127 - j; j++; }
            i = j + 1 + (t - s);
        } else if (t < 8256) {               // diagonal
            i = t - 8128; j = i;
        } else {                             // linear/bias rows
            j = 255; i = t - 8256;
        }
        sj = j; si = i;
        g_idx[t] = (uint16_t)((j << 8) | i);
    }
    __syncthreads();
    const int j = sj, i = si;
    float v;
    if (j == 255)      v = Wb[i * 128 + o] + bw[i * 128 + o];
    else if (j == i)   v = Ww[(size_t)i * 16384 + i * 128 + o];
    else               v = Ww[(size_t)j * 16384 + i * 128 + o]
                         + Ww[(size_t)i * 16384 + j * 128 + o];
    g_Ws[(size_t)t * 128 + (o & 7) * 16 + (o >> 3)] = tf32_rna(v);
}

// ---------------- main kernel ----------------
// SMEM: X[64][132]f @0 (33792) | idx u16[8384] @33792 (16768)
//       A frag-major [2][4mb][4ks][32lane][4]f @50560 (2x8192)
//       B permuted   [2][32k][132]f           @66944 (2x16896)
static constexpr int X_OFF = 0;
static constexpr int IDX_OFF = 33792;
static constexpr int A_OFF = 50560;
static constexpr int B_OFF = 66944;
static constexpr int SMEM_TOTAL = 100736;
static constexpr int NKB = 262;              // 8384 / 32

__global__ void __launch_bounds__(256) k_main(const float* __restrict__ x,
                                              const float* __restrict__ bb,
                                              float* __restrict__ y) {
    extern __shared__ char smem[];
    float*    sX   = (float*)(smem + X_OFF);
    uint16_t* sIdx = (uint16_t*)(smem + IDX_OFF);

    const int tid = threadIdx.x;
    const int m0 = blockIdx.x * 64;
    const int lane = tid & 31, wid = tid >> 5;
    const int wm = wid & 1, wn = wid >> 1;       // warp tile 32(M) x 32(N)
    const int gid = lane >> 2, tg = lane & 3;

    // Load X tile (64 x 128, smem row stride 132 floats)
    {
        const int r = tid >> 2, q = tid & 3;
        const float4* src = (const float4*)(x + (size_t)(m0 + r) * 128) + q * 8;
        float4* dst = (float4*)(sX + r * 132) + q * 8;
#pragma unroll
        for (int c = 0; c < 8; c++) dst[c] = src[c];
    }
    {
        const uint32_t* s = (const uint32_t*)g_idx;
        uint32_t* d = (uint32_t*)sIdx;
#pragma unroll
        for (int k = 0; k < 17; k++) {
            int e = tid + k * 256;
            if (e < 4192) d[e] = s[e];
        }
    }
    __syncthreads();

    // B staging: cp.async 16B chunks, row k padded to 132 floats
    auto cpasyncB = [&](int kb, int st) {
        const float* srcbase = g_Ws + (size_t)kb * 32 * 128;
        const uint32_t dstbase = smem_u32(smem + B_OFF + st * 16896);
#pragma unroll
        for (int c = 0; c < 4; c++) {
            const int chunk = tid + c * 256;          // 1024 chunks of 16B
            const int row = chunk >> 5, pos = chunk & 31;
            const float* src = srcbase + row * 128 + pos * 4;
            const uint32_t dst = dstbase + (uint32_t)(row * 528 + pos * 16);
            asm volatile("cp.async.cg.shared.global [%0], [%1], 16;"
                         :: "r"(dst), "l"(src));
        }
        asm volatile("cp.async.commit_group;");
    };

    // A builder: writes fragment quads directly. Quad Q -> A'[mb][ks][l][0..3]
    auto buildA = [&](int kb, int st) {
        float4* base = (float4*)(smem + A_OFF + st * 8192);
#pragma unroll
        for (int qq = 0; qq < 2; qq++) {
            const int Q = tid + qq * 256;
            const int mb = Q >> 7, ks = (Q >> 5) & 3, l = Q & 31;
            const int r = l >> 2, c = l & 3;
            const int mr0 = mb * 16 + r, mr1 = mr0 + 8;
            const int t0 = kb * 32 + ks * 8 + c, t1 = t0 + 4;
            const uint32_t e0 = sIdx[t0], e1 = sIdx[t1];
            const int i0 = e0 & 255, j0r = e0 >> 8;
            const int i1 = e1 & 255, j1r = e1 >> 8;
            const bool b0 = (j0r == 255), b1 = (j1r == 255);
            const int j0 = b0 ? 0 : j0r, j1 = b1 ? 0 : j1r;
            const float xi00 = sX[mr0 * 132 + i0], xi01 = sX[mr1 * 132 + i0];
            const float xi10 = sX[mr0 * 132 + i1], xi11 = sX[mr1 * 132 + i1];
            const float xj00 = b0 ? 1.0f : sX[mr0 * 132 + j0];
            const float xj01 = b0 ? 1.0f : sX[mr1 * 132 + j0];
            const float xj10 = b1 ? 1.0f : sX[mr0 * 132 + j1];
            const float xj11 = b1 ? 1.0f : sX[mr1 * 132 + j1];
            float4 w;
            w.x = tf32_rna(xi00 * xj00);   // A[mr0][t0]
            w.y = tf32_rna(xi01 * xj01);   // A[mr1][t0]
            w.z = tf32_rna(xi10 * xj10);   // A[mr0][t1]
            w.w = tf32_rna(xi11 * xj11);   // A[mr1][t1]
            base[Q] = w;
        }
    };

    // Prologue
    cpasyncB(0, 0);
    buildA(0, 0);
    asm volatile("cp.async.wait_group 0;");
    __syncthreads();

    float acc[2][4][4] = {};

    for (int kb = 0; kb < NKB; kb++) {
        const int cur = kb & 1, nxt = cur ^ 1;
        const bool pf = (kb + 1 < NKB);
        if (pf) { cpasyncB(kb + 1, nxt); buildA(kb + 1, nxt); }

        const float4* Af = (const float4*)(smem + A_OFF + cur * 8192);
        const float*  Bs = (const float*)(smem + B_OFF + cur * 16896);
#pragma unroll
        for (int ks = 0; ks < 4; ks++) {
            float4 a[2];
            a[0] = Af[((wm * 2 + 0) * 4 + ks) * 32 + lane];
            a[1] = Af[((wm * 2 + 1) * 4 + ks) * 32 + lane];
            // b frags: B'[k][gid*16 + wn*4 + nt]; components = nt 0..3
            const float4 bv0 = *(const float4*)(Bs + (ks * 8 + tg) * 132 + gid * 16 + wn * 4);
            const float4 bv1 = *(const float4*)(Bs + (ks * 8 + tg + 4) * 132 + gid * 16 + wn * 4);
            const float b0a[4] = {bv0.x, bv0.y, bv0.z, bv0.w};
            const float b1a[4] = {bv1.x, bv1.y, bv1.z, bv1.w};
#pragma unroll
            for (int mt = 0; mt < 2; mt++) {
                const uint32_t a0 = __float_as_uint(((const float*)&a[mt])[0]);
                const uint32_t a1 = __float_as_uint(((const float*)&a[mt])[1]);
                const uint32_t a2 = __float_as_uint(((const float*)&a[mt])[2]);
                const uint32_t a3 = __float_as_uint(((const float*)&a[mt])[3]);
#pragma unroll
                for (int nt = 0; nt < 4; nt++) {
                    asm volatile(
                        "mma.sync.aligned.m16n8k8.row.col.f32.tf32.tf32.f32 "
                        "{%0,%1,%2,%3}, {%4,%5,%6,%7}, {%8,%9}, {%0,%1,%2,%3};"
                        : "+f"(acc[mt][nt][0]), "+f"(acc[mt][nt][1]),
                          "+f"(acc[mt][nt][2]), "+f"(acc[mt][nt][3])
                        : "r"(a0), "r"(a1), "r"(a2), "r"(a3),
                          "r"(__float_as_uint(b0a[nt])), "r"(__float_as_uint(b1a[nt])));
                }
            }
        }
        if (pf) asm volatile("cp.async.wait_group 0;");
        __syncthreads();
    }

    // Epilogue: add bb, store float2 pairs
    const int mrow = m0 + wm * 32 + gid;
#pragma unroll
    for (int mt = 0; mt < 2; mt++) {
#pragma unroll
        for (int nt = 0; nt < 4; nt++) {
            const int n = wn * 32 + nt * 8 + tg * 2;
            const float c0 = __ldg(bb + n), c1 = __ldg(bb + n + 1);
            float* p0 = y + (size_t)(mrow + mt * 16) * 128 + n;
            float* p1 = p0 + 8 * 128;
            ((float2*)p0)[0] = make_float2(acc[mt][nt][0] + c0, acc[mt][nt][1] + c1);
            ((float2*)p1)[0] = make_float2(acc[mt][nt][2] + c0, acc[mt][nt][3] + c1);
        }
    }
}

extern "C" void kernel_launch(void* const* d_in, const int* in_sizes, int n_in,
                              void* d_out, int out_size) {
    const float* x  = (const float*)d_in[0];
    const float* Wb = (const float*)d_in[1];
    const float* bb = (const float*)d_in[2];
    const float* Ww = (const float*)d_in[3];
    const float* bw = (const float*)d_in[4];
    float* y = (float*)d_out;

    static bool attr_set = false;
    if (!attr_set) {
        cudaFuncSetAttribute(k_main, cudaFuncAttributeMaxDynamicSharedMemorySize, SMEM_TOTAL);
        attr_set = true;
    }

    k_prepW<<<8384, 128>>>(Ww, Wb, bw);
    k_main<<<128, 256, SMEM_TOTAL>>>(x, bb, y);
}